// round 7
// baseline (speedup 1.0000x reference)
#include <cuda_runtime.h>
#include <cstdint>
#include <cstddef>

typedef unsigned long long ull;

// 2-layer LSTM, B=512 T=1024 I=80 H=160, fp32, persistent 8-CTA-cluster kernel.
// 16 clusters x 8 ranks; cluster owns 32 batch (lanes), rank owns 20 h-rows.
// All weight slices SMEM-resident. h replicated per rank as k-PAIR float2
// layout, refreshed each step via st.shared::cluster. Inner product uses
// packed fma.rn.f32x2 (FFMA2) with even/odd-k partial sums.

#define HDIM   160
#define IDIM   80
#define TSTEPS 1024
#define CLUSTER 8
#define HS 20          // h rows per rank
#define GS 80          // gate rows per rank
#define NB 32          // batch per cluster (= lanes)
#define NTH 640        // 20 warps; warp w owns gate row w in each quarter
#define NCLUS 16
#define GRIDN (NCLUS*CLUSTER)
#define XSTR 33        // padded x-tile stride

// shared memory layout (float offsets)
#define OFF_W0   0        // W_hh0 slice [GS][HDIM]
#define OFF_WI1  12800    // W_ih1 slice [GS][HDIM]
#define OFF_WH1  25600    // W_hh1 slice [GS][HDIM]
#define OFF_WI0  38400    // W_ih0 slice [GS][IDIM]
#define OFF_HP0  44800    // h0 replica as float2 pairs [80][NB]
#define OFF_HP1  49920    // h1 replica as float2 pairs [80][NB]
#define OFF_XS   55040    // x tile [IDIM][XSTR] transposed, padded
#define OFF_B0   57680    // fused bias layer0 slice [GS]
#define OFF_B1   57760    // fused bias layer1 slice [GS]
#define OFF_WOUT 57840    // W_out [HDIM]
#define OFF_BOUT 58000
#define SMEM_FLOATS 58004
#define SMEM_BYTES (SMEM_FLOATS*4)   // 232016 B <= 232448 max dyn smem

__device__ __forceinline__ uint32_t smem_u32(const void* p){
    uint32_t a;
    asm("{ .reg .u64 t; cvta.to.shared.u64 t, %1; cvt.u32.u64 %0, t; }"
        : "=r"(a) : "l"(p));
    return a;
}
__device__ __forceinline__ uint32_t mapa_rank(uint32_t addr, uint32_t r){
    uint32_t d;
    asm("mapa.shared::cluster.u32 %0, %1, %2;" : "=r"(d) : "r"(addr), "r"(r));
    return d;
}
__device__ __forceinline__ void st_cluster_f32(uint32_t addr, float v){
    asm volatile("st.shared::cluster.f32 [%0], %1;" :: "r"(addr), "f"(v));
}
__device__ __forceinline__ void cluster_sync_all(){
    asm volatile("barrier.cluster.arrive.aligned;" ::: "memory");
    asm volatile("barrier.cluster.wait.aligned;"   ::: "memory");
}
__device__ __forceinline__ uint32_t ctarank(){
    uint32_t r; asm("mov.u32 %0, %%cluster_ctarank;" : "=r"(r)); return r;
}

// packed fp32x2 FMA: a = b*c + a (lanewise, exact fp32)
__device__ __forceinline__ void ffma2(ull &a, ull b, ull c){
    asm("fma.rn.f32x2 %0, %1, %2, %0;" : "+l"(a) : "l"(b), "l"(c));
}
__device__ __forceinline__ ull pack2(float lo, float hi){
    ull r; asm("mov.b64 %0, {%1,%2};" : "=l"(r) : "f"(lo), "f"(hi)); return r;
}
__device__ __forceinline__ float sum2(ull v){
    float lo, hi; asm("mov.b64 {%0,%1}, %2;" : "=f"(lo), "=f"(hi) : "l"(v));
    return lo + hi;
}
// saturating-safe fast activations (abs err ~1e-7, fine vs 1e-3 budget)
__device__ __forceinline__ float sigm(float x){
    return __fdividef(1.0f, 1.0f + __expf(-x));
}
__device__ __forceinline__ float tanhfast(float x){
    return 2.0f*__fdividef(1.0f, 1.0f + __expf(-2.0f*x)) - 1.0f;
}

// acc[q] (f32x2) += W[(q*HS+w)][:] . h[:]  over K, k-pair packed.
// W rows read as ulonglong2 (one LDS.128 = 2 packed pairs, no pack instrs);
// h read as LDS.64 pairs from the interleaved float2 replica.
template<int K>
__device__ __forceinline__ void mmh4(ull acc[4], const float* __restrict__ Wsm,
                                     int w, const ull* __restrict__ hp){
    const ulonglong2* W0 = reinterpret_cast<const ulonglong2*>(Wsm + (0*HS + w)*K);
    const ulonglong2* W1 = reinterpret_cast<const ulonglong2*>(Wsm + (1*HS + w)*K);
    const ulonglong2* W2 = reinterpret_cast<const ulonglong2*>(Wsm + (2*HS + w)*K);
    const ulonglong2* W3 = reinterpret_cast<const ulonglong2*>(Wsm + (3*HS + w)*K);
    #pragma unroll 4
    for (int kk = 0; kk < K/4; kk++){
        ull h01 = hp[(2*kk  )*NB];
        ull h23 = hp[(2*kk+1)*NB];
        ulonglong2 a = W0[kk]; ffma2(acc[0], a.x, h01); ffma2(acc[0], a.y, h23);
        ulonglong2 b = W1[kk]; ffma2(acc[1], b.x, h01); ffma2(acc[1], b.y, h23);
        ulonglong2 c = W2[kk]; ffma2(acc[2], c.x, h01); ffma2(acc[2], c.y, h23);
        ulonglong2 d = W3[kk]; ffma2(acc[3], d.x, h01); ffma2(acc[3], d.y, h23);
    }
}

// x part: scalar padded tile, pack at load (only 20 iterations)
__device__ __forceinline__ void mmx4(ull acc[4], const float* __restrict__ Wsm,
                                     int w, const float* __restrict__ xp){
    const ulonglong2* W0 = reinterpret_cast<const ulonglong2*>(Wsm + (0*HS + w)*IDIM);
    const ulonglong2* W1 = reinterpret_cast<const ulonglong2*>(Wsm + (1*HS + w)*IDIM);
    const ulonglong2* W2 = reinterpret_cast<const ulonglong2*>(Wsm + (2*HS + w)*IDIM);
    const ulonglong2* W3 = reinterpret_cast<const ulonglong2*>(Wsm + (3*HS + w)*IDIM);
    #pragma unroll 4
    for (int kk = 0; kk < IDIM/4; kk++){
        float x0 = xp[(4*kk+0)*XSTR];
        float x1 = xp[(4*kk+1)*XSTR];
        float x2 = xp[(4*kk+2)*XSTR];
        float x3 = xp[(4*kk+3)*XSTR];
        ull h01 = pack2(x0, x1);
        ull h23 = pack2(x2, x3);
        ulonglong2 a = W0[kk]; ffma2(acc[0], a.x, h01); ffma2(acc[0], a.y, h23);
        ulonglong2 b = W1[kk]; ffma2(acc[1], b.x, h01); ffma2(acc[1], b.y, h23);
        ulonglong2 c = W2[kk]; ffma2(acc[2], c.x, h01); ffma2(acc[2], c.y, h23);
        ulonglong2 d = W3[kk]; ffma2(acc[3], d.x, h01); ffma2(acc[3], d.y, h23);
    }
}

__global__ void __cluster_dims__(CLUSTER,1,1) __launch_bounds__(NTH,1)
lstm2_kernel(const float* __restrict__ x,
             const float* __restrict__ Wih0, const float* __restrict__ Whh0,
             const float* __restrict__ bih0, const float* __restrict__ bhh0,
             const float* __restrict__ Wih1, const float* __restrict__ Whh1,
             const float* __restrict__ bih1, const float* __restrict__ bhh1,
             const float* __restrict__ Wout, const float* __restrict__ bout,
             float* __restrict__ out)
{
    extern __shared__ float sm[];
    const int tid  = threadIdx.x;
    const int lane = tid & 31;
    const int w    = tid >> 5;        // 0..19, gate row within each quarter
    const uint32_t rank = ctarank();
    const int cidx = blockIdx.x / CLUSTER;
    const int b0g  = cidx * NB;
    const int hb   = (int)rank * HS;

    // ---- persistent weight slices -> SMEM ----
    for (int idx = tid; idx < GS*HDIM; idx += NTH){
        int lr = idx / HDIM, k = idx - lr*HDIM;
        int q = lr / HS, j = lr - q*HS;
        int grow = q*HDIM + hb + j;           // pytorch gate order i,f,g,o
        sm[OFF_W0  + idx] = Whh0[grow*HDIM + k];
        sm[OFF_WI1 + idx] = Wih1[grow*HDIM + k];
        sm[OFF_WH1 + idx] = Whh1[grow*HDIM + k];
    }
    for (int idx = tid; idx < GS*IDIM; idx += NTH){
        int lr = idx / IDIM, k = idx - lr*IDIM;
        int q = lr / HS, j = lr - q*HS;
        int grow = q*HDIM + hb + j;
        sm[OFF_WI0 + idx] = Wih0[grow*IDIM + k];
    }
    for (int idx = tid; idx < GS; idx += NTH){
        int q = idx / HS, j = idx - q*HS;
        int grow = q*HDIM + hb + j;
        sm[OFF_B0 + idx] = bih0[grow] + bhh0[grow];
        sm[OFF_B1 + idx] = bih1[grow] + bhh1[grow];
    }
    for (int idx = tid; idx < HDIM; idx += NTH) sm[OFF_WOUT + idx] = Wout[idx];
    if (tid == 0) sm[OFF_BOUT] = bout[0];
    for (int idx = tid; idx < HDIM*NB; idx += NTH){
        sm[OFF_HP0 + idx] = 0.0f;
        sm[OFF_HP1 + idx] = 0.0f;
    }
    float c0 = 0.f, c1 = 0.f;
    cluster_sync_all();

    // broadcast addresses: this warp produces h row g; pair slot (g&1)
    const int g = hb + w;
    const uint32_t o0 = smem_u32(&sm[OFF_HP0 + ((g>>1)*NB + lane)*2 + (g&1)]);
    const uint32_t o1 = smem_u32(&sm[OFF_HP1 + ((g>>1)*NB + lane)*2 + (g&1)]);
    uint32_t ad0[CLUSTER], ad1[CLUSTER];
    #pragma unroll
    for (uint32_t r = 0; r < CLUSTER; r++){
        ad0[r] = mapa_rank(o0, r);
        ad1[r] = mapa_rank(o1, r);
    }

    float b0r[4], b1r[4];
    #pragma unroll
    for (int q = 0; q < 4; q++){
        b0r[q] = sm[OFF_B0 + q*HS + w];
        b1r[q] = sm[OFF_B1 + q*HS + w];
    }

    const float* __restrict__ xg = x + (size_t)b0g * TSTEPS * IDIM;
    const ull* hp0 = reinterpret_cast<const ull*>(&sm[OFF_HP0]) + lane;
    const ull* hp1 = reinterpret_cast<const ull*>(&sm[OFF_HP1]) + lane;
    const float* xp = &sm[OFF_XS] + lane;

    for (int t = 0; t < TSTEPS; t++){
        // prefetch this step's x (LDG in flight during recurrent matmul)
        float xv[4]; int xo[4];
        #pragma unroll
        for (int u = 0; u < 4; u++){
            int idx = tid + u*NTH;               // 0..2559
            int b = idx / IDIM, i = idx - b*IDIM;
            xv[u] = xg[(size_t)b*TSTEPS*IDIM + (size_t)t*IDIM + i];
            xo[u] = i*XSTR + b;
        }

        // ---- layer 0: recurrent part first (hides x LDG) ----
        ull acc[4];
        #pragma unroll
        for (int q = 0; q < 4; q++) acc[q] = pack2(b0r[q], 0.f);
        mmh4<HDIM>(acc, &sm[OFF_W0], w, hp0);

        // stage x (prev readers drained by prev step's cluster syncs)
        #pragma unroll
        for (int u = 0; u < 4; u++) sm[OFF_XS + xo[u]] = xv[u];
        __syncthreads();
        mmx4(acc, &sm[OFF_WI0], w, xp);

        float gi = sum2(acc[0]), gf = sum2(acc[1]);
        float gg = sum2(acc[2]), go = sum2(acc[3]);
        c0 = sigm(gf)*c0 + sigm(gi)*tanhfast(gg);
        float hn0 = sigm(go)*tanhfast(c0);

        cluster_sync_all();                       // all ranks done reading h0
        #pragma unroll
        for (uint32_t r = 0; r < CLUSTER; r++) st_cluster_f32(ad0[r], hn0);
        cluster_sync_all();                       // new h0 visible everywhere

        // ---- layer 1 ----
        ull a1[4];
        #pragma unroll
        for (int q = 0; q < 4; q++) a1[q] = pack2(b1r[q], 0.f);
        mmh4<HDIM>(a1, &sm[OFF_WI1], w, hp0);
        mmh4<HDIM>(a1, &sm[OFF_WH1], w, hp1);

        gi = sum2(a1[0]); gf = sum2(a1[1]);
        gg = sum2(a1[2]); go = sum2(a1[3]);
        c1 = sigm(gf)*c1 + sigm(gi)*tanhfast(gg);
        float hn1 = sigm(go)*tanhfast(c1);

        cluster_sync_all();                       // all ranks done reading h1
        #pragma unroll
        for (uint32_t r = 0; r < CLUSTER; r++) st_cluster_f32(ad1[r], hn1);
        cluster_sync_all();                       // new h1 visible everywhere

        // ---- output head: warp 0, lane = batch ----
        if (w == 0){
            ull s = pack2(sm[OFF_BOUT], 0.f);
            const ull* wo = reinterpret_cast<const ull*>(&sm[OFF_WOUT]);
            #pragma unroll 8
            for (int j2 = 0; j2 < HDIM/2; j2++)
                ffma2(s, wo[j2], hp1[j2*NB]);
            float y = sum2(s);
            out[(size_t)(b0g + lane)*TSTEPS + t] = fmaxf(y, 0.0f);
        }
    }
}

extern "C" void kernel_launch(void* const* d_in, const int* in_sizes, int n_in,
                              void* d_out, int out_size) {
    (void)in_sizes; (void)n_in; (void)out_size;
    const float* x    = (const float*)d_in[0];
    const float* Wih0 = (const float*)d_in[1];
    const float* Whh0 = (const float*)d_in[2];
    const float* bih0 = (const float*)d_in[3];
    const float* bhh0 = (const float*)d_in[4];
    const float* Wih1 = (const float*)d_in[5];
    const float* Whh1 = (const float*)d_in[6];
    const float* bih1 = (const float*)d_in[7];
    const float* bhh1 = (const float*)d_in[8];
    const float* Wout = (const float*)d_in[9];
    const float* bout = (const float*)d_in[10];
    float* out = (float*)d_out;

    cudaFuncSetAttribute(lstm2_kernel,
                         cudaFuncAttributeMaxDynamicSharedMemorySize, SMEM_BYTES);
    lstm2_kernel<<<GRIDN, NTH, SMEM_BYTES>>>(x, Wih0, Whh0, bih0, bhh0,
                                             Wih1, Whh1, bih1, bhh1,
                                             Wout, bout, out);
}

// round 9
// speedup vs baseline: 1.2287x; 1.2287x over previous
#include <cuda_runtime.h>
#include <cstdint>
#include <cstddef>

typedef unsigned long long ull;

// 2-layer LSTM, B=512 T=1024 I=80 H=160, fp32, persistent 8-CTA-cluster kernel.
// 16 clusters x 8 ranks; cluster owns 32 batch (lanes), rank owns 20 h-rows
// (80 gate rows/layer), all weight slices SMEM-resident. h replicated per rank
// as k-pair float2 layout, refreshed via st.shared::cluster.b64.
// Synchronization: DSMEM mbarriers (consumed/ready per layer, count=8,
// parity=t&1) with overlapped waits — no barrier.cluster in the loop.

#define HDIM   160
#define IDIM   80
#define TSTEPS 1024
#define CLUSTER 8
#define HS 20          // h rows per rank
#define GS 80          // gate rows per rank
#define NB 32          // batch per cluster (= lanes)
#define NTH 320        // 10 warps; warp w owns rows {2w,2w+1} of each quarter
#define NCLUS 16
#define GRIDN (NCLUS*CLUSTER)
#define XSTR 33        // padded x-tile stride

// shared memory layout (float offsets)
#define OFF_W0   0        // W_hh0 slice [GS][HDIM]
#define OFF_WH1  12800    // W_hh1 slice [GS][HDIM]
#define OFF_WI1  25600    // W_ih1 slice [GS][HDIM]
#define OFF_WI0  38400    // W_ih0 slice [GS][IDIM]
#define OFF_HP0  44800    // h0 replica as k-pairs [80][NB] (ull)
#define OFF_HP1  49920    // h1 replica as k-pairs [80][NB] (ull)
#define OFF_XS   55040    // x tile [IDIM][XSTR] transposed, padded
#define OFF_B0   57680    // fused bias layer0 slice [GS]
#define OFF_B1   57760    // fused bias layer1 slice [GS]
#define OFF_WOUT 57840    // W_out [HDIM]
#define OFF_BOUT 58000
#define OFF_MBAR 58004    // 4 mbarriers (u64 each) at byte 232016, 8B aligned
#define SMEM_FLOATS 58012
#define SMEM_BYTES (SMEM_FLOATS*4)   // 232048 B <= 232448

// mbarrier byte offsets from smem base
#define MB_C0 (OFF_MBAR*4 + 0)   // h0 consumed
#define MB_R0 (OFF_MBAR*4 + 8)   // h0 ready
#define MB_C1 (OFF_MBAR*4 + 16)  // h1 consumed
#define MB_R1 (OFF_MBAR*4 + 24)  // h1 ready

__device__ __forceinline__ uint32_t smem_u32(const void* p){
    uint32_t a;
    asm("{ .reg .u64 t; cvta.to.shared.u64 t, %1; cvt.u32.u64 %0, t; }"
        : "=r"(a) : "l"(p));
    return a;
}
__device__ __forceinline__ uint32_t mapa_rank(uint32_t addr, uint32_t r){
    uint32_t d;
    asm("mapa.shared::cluster.u32 %0, %1, %2;" : "=r"(d) : "r"(addr), "r"(r));
    return d;
}
__device__ __forceinline__ void st_cluster_b64(uint32_t addr, ull v){
    asm volatile("st.shared::cluster.b64 [%0], %1;" :: "r"(addr), "l"(v));
}
__device__ __forceinline__ uint32_t ctarank(){
    uint32_t r; asm("mov.u32 %0, %%cluster_ctarank;" : "=r"(r)); return r;
}
__device__ __forceinline__ void mbar_init(uint32_t addr, uint32_t cnt){
    asm volatile("mbarrier.init.shared.b64 [%0], %1;" :: "r"(addr), "r"(cnt)
                 : "memory");
}
// arrive (release, cluster scope) on the same-offset barrier in every rank
__device__ __forceinline__ void mbar_arrive_all(uint32_t local_addr){
    #pragma unroll
    for (uint32_t r = 0; r < CLUSTER; r++){
        uint32_t ra = mapa_rank(local_addr, r);
        asm volatile(
            "mbarrier.arrive.release.cluster.shared::cluster.b64 _, [%0];"
            :: "r"(ra) : "memory");
    }
}
// wait on LOCAL barrier for phase of given parity (acquire, cluster scope)
__device__ __forceinline__ void mbar_wait(uint32_t addr, uint32_t parity){
    uint32_t done;
    asm volatile(
        "{ .reg .pred p;\n\t"
        "mbarrier.try_wait.parity.acquire.cluster.shared::cta.b64 p, [%1], %2;\n\t"
        "selp.b32 %0, 1, 0, p; }"
        : "=r"(done) : "r"(addr), "r"(parity) : "memory");
    while (!done){
        asm volatile(
            "{ .reg .pred p;\n\t"
            "mbarrier.try_wait.parity.acquire.cluster.shared::cta.b64 p, [%1], %2, 0x989680;\n\t"
            "selp.b32 %0, 1, 0, p; }"
            : "=r"(done) : "r"(addr), "r"(parity) : "memory");
    }
}

// packed fp32x2 FMA: a = b*c + a (lanewise, exact fp32)
__device__ __forceinline__ void ffma2(ull &a, ull b, ull c){
    asm("fma.rn.f32x2 %0, %1, %2, %0;" : "+l"(a) : "l"(b), "l"(c));
}
__device__ __forceinline__ ull pack2(float lo, float hi){
    ull r; asm("mov.b64 %0, {%1,%2};" : "=l"(r) : "f"(lo), "f"(hi)); return r;
}
__device__ __forceinline__ float sum2(ull v){
    float lo, hi; asm("mov.b64 {%0,%1}, %2;" : "=f"(lo), "=f"(hi) : "l"(v));
    return lo + hi;
}
__device__ __forceinline__ float sigm(float x){
    return __fdividef(1.0f, 1.0f + __expf(-x));
}
__device__ __forceinline__ float tanhfast(float x){
    return 2.0f*__fdividef(1.0f, 1.0f + __expf(-2.0f*x)) - 1.0f;
}

// acc[2q+p] (f32x2, even/odd-k partials) += W[(q*HS+r0+p)][:] . h[:]
// W rows via warp-uniform LDS.128 (ulonglong2 = 2 packed k-pairs);
// h via lane-consecutive LDS.64 pairs, prefetched one iteration ahead.
template<int K>
__device__ __forceinline__ void mm8h(ull acc[8], const float* __restrict__ Wsm,
                                     int r0, const ull* __restrict__ hp){
    const ulonglong2* W[8];
    #pragma unroll
    for (int q = 0; q < 4; q++){
        W[2*q]   = reinterpret_cast<const ulonglong2*>(Wsm + (q*HS + r0    )*K);
        W[2*q+1] = reinterpret_cast<const ulonglong2*>(Wsm + (q*HS + r0 + 1)*K);
    }
    ull h01 = hp[0], h23 = hp[NB];
    #pragma unroll 8
    for (int kk = 0; kk < K/4; kk++){
        ull n01 = 0, n23 = 0;
        if (kk + 1 < K/4){ n01 = hp[(2*kk+2)*NB]; n23 = hp[(2*kk+3)*NB]; }
        #pragma unroll
        for (int r = 0; r < 8; r++){
            ulonglong2 wv = W[r][kk];
            ffma2(acc[r], wv.x, h01);
            ffma2(acc[r], wv.y, h23);
        }
        h01 = n01; h23 = n23;
    }
}

// x part: scalar padded tile, packed at load
__device__ __forceinline__ void mm8x(ull acc[8], const float* __restrict__ Wsm,
                                     int r0, const float* __restrict__ xp){
    const ulonglong2* W[8];
    #pragma unroll
    for (int q = 0; q < 4; q++){
        W[2*q]   = reinterpret_cast<const ulonglong2*>(Wsm + (q*HS + r0    )*IDIM);
        W[2*q+1] = reinterpret_cast<const ulonglong2*>(Wsm + (q*HS + r0 + 1)*IDIM);
    }
    #pragma unroll 5
    for (int kk = 0; kk < IDIM/4; kk++){
        ull x01 = pack2(xp[(4*kk+0)*XSTR], xp[(4*kk+1)*XSTR]);
        ull x23 = pack2(xp[(4*kk+2)*XSTR], xp[(4*kk+3)*XSTR]);
        #pragma unroll
        for (int r = 0; r < 8; r++){
            ulonglong2 wv = W[r][kk];
            ffma2(acc[r], wv.x, x01);
            ffma2(acc[r], wv.y, x23);
        }
    }
}

__global__ void __cluster_dims__(CLUSTER,1,1) __launch_bounds__(NTH,1)
lstm2_kernel(const float* __restrict__ x,
             const float* __restrict__ Wih0, const float* __restrict__ Whh0,
             const float* __restrict__ bih0, const float* __restrict__ bhh0,
             const float* __restrict__ Wih1, const float* __restrict__ Whh1,
             const float* __restrict__ bih1, const float* __restrict__ bhh1,
             const float* __restrict__ Wout, const float* __restrict__ bout,
             float* __restrict__ out)
{
    extern __shared__ float sm[];
    const int tid  = threadIdx.x;
    const int lane = tid & 31;
    const int w    = tid >> 5;        // 0..9
    const int r0   = 2*w;             // local rows r0, r0+1 per quarter
    const uint32_t rank = ctarank();
    const int cidx = blockIdx.x / CLUSTER;
    const int b0g  = cidx * NB;
    const int hb   = (int)rank * HS;
    const uint32_t smb = smem_u32(sm);

    // ---- persistent weight slices -> SMEM ----
    for (int idx = tid; idx < GS*HDIM; idx += NTH){
        int lr = idx / HDIM, k = idx - lr*HDIM;
        int q = lr / HS, j = lr - q*HS;
        int grow = q*HDIM + hb + j;           // pytorch gate order i,f,g,o
        sm[OFF_W0  + idx] = Whh0[grow*HDIM + k];
        sm[OFF_WH1 + idx] = Whh1[grow*HDIM + k];
        sm[OFF_WI1 + idx] = Wih1[grow*HDIM + k];
    }
    for (int idx = tid; idx < GS*IDIM; idx += NTH){
        int lr = idx / IDIM, k = idx - lr*IDIM;
        int q = lr / HS, j = lr - q*HS;
        int grow = q*HDIM + hb + j;
        sm[OFF_WI0 + idx] = Wih0[grow*IDIM + k];
    }
    for (int idx = tid; idx < GS; idx += NTH){
        int q = idx / HS, j = idx - q*HS;
        int grow = q*HDIM + hb + j;
        sm[OFF_B0 + idx] = bih0[grow] + bhh0[grow];
        sm[OFF_B1 + idx] = bih1[grow] + bhh1[grow];
    }
    for (int idx = tid; idx < HDIM; idx += NTH) sm[OFF_WOUT + idx] = Wout[idx];
    if (tid == 0) sm[OFF_BOUT] = bout[0];
    for (int idx = tid; idx < HDIM*NB; idx += NTH){
        sm[OFF_HP0 + idx] = 0.0f;
        sm[OFF_HP1 + idx] = 0.0f;
    }
    if (tid == 0){
        mbar_init(smb + MB_C0, CLUSTER);
        mbar_init(smb + MB_R0, CLUSTER);
        mbar_init(smb + MB_C1, CLUSTER);
        mbar_init(smb + MB_R1, CLUSTER);
    }
    float c0a = 0.f, c0b = 0.f, c1a = 0.f, c1b = 0.f;
    __syncthreads();
    // all inits + zeroed replicas visible cluster-wide before any remote op
    asm volatile("barrier.cluster.arrive.aligned;" ::: "memory");
    asm volatile("barrier.cluster.wait.aligned;"   ::: "memory");

    // pair slot this warp produces: pair index rank*10 + w, element = lane
    const uint32_t o0 = smem_u32(reinterpret_cast<ull*>(&sm[OFF_HP0])
                                 + ((int)rank*10 + w)*NB + lane);
    const uint32_t o1 = smem_u32(reinterpret_cast<ull*>(&sm[OFF_HP1])
                                 + ((int)rank*10 + w)*NB + lane);
    uint32_t ad0[CLUSTER], ad1[CLUSTER];
    #pragma unroll
    for (uint32_t r = 0; r < CLUSTER; r++){
        ad0[r] = mapa_rank(o0, r);
        ad1[r] = mapa_rank(o1, r);
    }

    float b0r[8], b1r[8];
    #pragma unroll
    for (int q = 0; q < 4; q++){
        b0r[2*q]   = sm[OFF_B0 + q*HS + r0];
        b0r[2*q+1] = sm[OFF_B0 + q*HS + r0 + 1];
        b1r[2*q]   = sm[OFF_B1 + q*HS + r0];
        b1r[2*q+1] = sm[OFF_B1 + q*HS + r0 + 1];
    }

    // x prefetch addressing: 8 elements/thread, fixed (b,i) per slot
    const float* xg = x + (size_t)b0g * TSTEPS * IDIM;
    const float* gptr[8]; int xo[8];
    #pragma unroll
    for (int u = 0; u < 8; u++){
        int idx = tid + u*NTH;                 // 0..2559
        int b = idx / IDIM, i = idx - b*IDIM;
        gptr[u] = xg + (size_t)b*TSTEPS*IDIM + i;
        xo[u]   = OFF_XS + i*XSTR + b;
    }

    const ull* hp0 = reinterpret_cast<const ull*>(&sm[OFF_HP0]) + lane;
    const ull* hp1 = reinterpret_cast<const ull*>(&sm[OFF_HP1]) + lane;
    const float* xp = &sm[OFF_XS] + lane;
    const ull* wo = reinterpret_cast<const ull*>(&sm[OFF_WOUT]);
    const float boutv = bout[0];
    float* const orow = out + (size_t)(b0g + lane)*TSTEPS;

    for (int t = 0; t < TSTEPS; t++){
        const uint32_t par = (uint32_t)(t & 1);

        // x(t) LDG in flight during layer-0 recurrent matmul
        float xv[8];
        #pragma unroll
        for (int u = 0; u < 8; u++) xv[u] = gptr[u][(size_t)t*IDIM];

        // layer 0 recurrent (reads h0(t-1), local replica)
        ull acc[8];
        #pragma unroll
        for (int r = 0; r < 8; r++) acc[r] = pack2(b0r[r], 0.f);
        mm8h<HDIM>(acc, &sm[OFF_W0], r0, hp0);

        // stage x(t); the barrier also marks "this CTA done reading h0(t-1)"
        #pragma unroll
        for (int u = 0; u < 8; u++) sm[xo[u]] = xv[u];
        __syncthreads();
        if (tid == 0) mbar_arrive_all(smb + MB_C0);

        mm8x(acc, &sm[OFF_WI0], r0, xp);

        float hn0a, hn0b;
        {
            float gi = sigm(sum2(acc[0])), gf = sigm(sum2(acc[2]));
            float gg = tanhfast(sum2(acc[4])), go = sigm(sum2(acc[6]));
            c0a = gf*c0a + gi*gg;  hn0a = go*tanhfast(c0a);
            gi = sigm(sum2(acc[1])); gf = sigm(sum2(acc[3]));
            gg = tanhfast(sum2(acc[5])); go = sigm(sum2(acc[7]));
            c0b = gf*c0b + gi*gg;  hn0b = go*tanhfast(c0b);
        }

        mbar_wait(smb + MB_C0, par);        // all ranks done reading h0(t-1)
        {
            ull hv = pack2(hn0a, hn0b);
            #pragma unroll
            for (uint32_t r = 0; r < CLUSTER; r++) st_cluster_b64(ad0[r], hv);
        }
        __syncthreads();                    // this CTA's h0 stores issued
        if (tid == 0) mbar_arrive_all(smb + MB_R0);

        // layer 1 part A: W_hh1 . h1(t-1)  (overlaps h0 propagation)
        ull a1c[8];
        #pragma unroll
        for (int r = 0; r < 8; r++) a1c[r] = pack2(b1r[r], 0.f);
        mm8h<HDIM>(a1c, &sm[OFF_WH1], r0, hp1);

        __syncthreads();                    // this CTA done reading h1(t-1)
        if (tid == 0) mbar_arrive_all(smb + MB_C1);

        mbar_wait(smb + MB_R0, par);        // h0(t) visible everywhere
        mm8h<HDIM>(a1c, &sm[OFF_WI1], r0, hp0);

        float hn1a, hn1b;
        {
            float gi = sigm(sum2(a1c[0])), gf = sigm(sum2(a1c[2]));
            float gg = tanhfast(sum2(a1c[4])), go = sigm(sum2(a1c[6]));
            c1a = gf*c1a + gi*gg;  hn1a = go*tanhfast(c1a);
            gi = sigm(sum2(a1c[1])); gf = sigm(sum2(a1c[3]));
            gg = tanhfast(sum2(a1c[5])); go = sigm(sum2(a1c[7]));
            c1b = gf*c1b + gi*gg;  hn1b = go*tanhfast(c1b);
        }

        mbar_wait(smb + MB_C1, par);        // all ranks done reading h1(t-1)
        {
            ull hv = pack2(hn1a, hn1b);
            #pragma unroll
            for (uint32_t r = 0; r < CLUSTER; r++) st_cluster_b64(ad1[r], hv);
        }
        __syncthreads();                    // this CTA's h1 stores issued
        if (tid == 0) mbar_arrive_all(smb + MB_R1);

        mbar_wait(smb + MB_R1, par);        // h1(t) visible everywhere

        // output head: warp 0, lane = batch
        if (w == 0){
            ull s0 = pack2(boutv, 0.f), s1 = 0, s2 = 0, s3 = 0;
            #pragma unroll 10
            for (int p = 0; p < HDIM/2; p += 4){
                ffma2(s0, wo[p  ], hp1[(p  )*NB]);
                ffma2(s1, wo[p+1], hp1[(p+1)*NB]);
                ffma2(s2, wo[p+2], hp1[(p+2)*NB]);
                ffma2(s3, wo[p+3], hp1[(p+3)*NB]);
            }
            float y = (sum2(s0) + sum2(s1)) + (sum2(s2) + sum2(s3));
            orow[t] = fmaxf(y, 0.0f);
        }
    }
    // keep cluster resident until all ranks finish (writers target peer SMEM)
    asm volatile("barrier.cluster.arrive.aligned;" ::: "memory");
    asm volatile("barrier.cluster.wait.aligned;"   ::: "memory");
}

extern "C" void kernel_launch(void* const* d_in, const int* in_sizes, int n_in,
                              void* d_out, int out_size) {
    (void)in_sizes; (void)n_in; (void)out_size;
    const float* x    = (const float*)d_in[0];
    const float* Wih0 = (const float*)d_in[1];
    const float* Whh0 = (const float*)d_in[2];
    const float* bih0 = (const float*)d_in[3];
    const float* bhh0 = (const float*)d_in[4];
    const float* Wih1 = (const float*)d_in[5];
    const float* Whh1 = (const float*)d_in[6];
    const float* bih1 = (const float*)d_in[7];
    const float* bhh1 = (const float*)d_in[8];
    const float* Wout = (const float*)d_in[9];
    const float* bout = (const float*)d_in[10];
    float* out = (float*)d_out;

    cudaFuncSetAttribute(lstm2_kernel,
                         cudaFuncAttributeMaxDynamicSharedMemorySize, SMEM_BYTES);
    lstm2_kernel<<<GRIDN, NTH, SMEM_BYTES>>>(x, Wih0, Whh0, bih0, bhh0,
                                             Wih1, Whh1, bih1, bhh1,
                                             Wout, bout, out);
}